// round 1
// baseline (speedup 1.0000x reference)
#include <cuda_runtime.h>

// Problem constants (shapes are fixed by the dataset; code stays correct for
// any batch_list via the offsets kernel + fallback path).
#define D_DIM   300          // embedding dim
#define DC      100          // columns per chunk (multiple of 4, divides 300)
#define DC4     (DC / 4)     // 25 float4 per row-chunk
#define NCHUNK  (D_DIM / DC) // 3
#define TR      256          // row tile (== nodes per graph in this dataset)
#define NT      256          // threads per CTA
#define MAXB    8192
#define EPSV    1e-12f

// Scratch (no cudaMalloc allowed): per-graph row offsets + actual graph count.
__device__ int g_off[MAXB + 1];
__device__ int g_B;

// ---------------------------------------------------------------------------
// Offsets kernel: detects int32 vs int64 batch_list layout, inclusive-scans
// node counts into g_off, resolves the element-count convention by checking
// the total against ntot (= number of nodes).
// ---------------------------------------------------------------------------
__global__ void offsets_kernel(const int* __restrict__ p32, int nb, int ntot) {
    __shared__ int sh[1024];
    __shared__ int s_stride, s_carry;
    const int tid = threadIdx.x;

    if (tid == 0) {
        // int64 little-endian: odd int32 lanes are the (zero) high words.
        int stride = 1;
        if (nb > 1) {
            int v0 = p32[0], v1 = p32[1];
            if (v1 == 0 && v0 != 0) stride = 2;
        }
        s_stride = stride;
        s_carry = 0;
        g_off[0] = 0;
    }
    __syncthreads();

    const int st = s_stride;
    int B = nb;
    if (B > MAXB) B = MAXB;
    // If int64: first scan only nb/2 entries (safe under both element-count
    // conventions), extend to nb only if the total doesn't match ntot.
    const int B1 = (st == 2) ? (B >> 1) : B;

    // scan [0, B1)
    for (int base = 0; base < B1; base += 1024) {
        int i = base + tid;
        int v = (i < B1) ? p32[(size_t)i * st] : 0;
        sh[tid] = v;
        __syncthreads();
        #pragma unroll
        for (int o = 1; o < 1024; o <<= 1) {
            int t = (tid >= o) ? sh[tid - o] : 0;
            __syncthreads();
            sh[tid] += t;
            __syncthreads();
        }
        if (i < B1) g_off[i + 1] = s_carry + sh[tid];
        __syncthreads();
        if (tid == 0) s_carry += sh[1023];
        __syncthreads();
    }

    int Bfinal = B1;
    if (st == 2 && B1 > 0 && g_off[B1] != ntot && B > B1) {
        // int64 buffer with nb counted as int64 elements: scan the rest.
        for (int base = B1; base < B; base += 1024) {
            int i = base + tid;
            int v = (i < B) ? p32[(size_t)i * st] : 0;
            sh[tid] = v;
            __syncthreads();
            #pragma unroll
            for (int o = 1; o < 1024; o <<= 1) {
                int t = (tid >= o) ? sh[tid - o] : 0;
                __syncthreads();
                sh[tid] += t;
                __syncthreads();
            }
            if (i < B) g_off[i + 1] = s_carry + sh[tid];
            __syncthreads();
            if (tid == 0) s_carry += sh[1023];
            __syncthreads();
        }
        Bfinal = B;
    }
    if (tid == 0) g_B = Bfinal;
}

// ---------------------------------------------------------------------------
// Main kernel: one CTA per (graph, column-chunk). Fast path (nr <= TR):
// tile -> smem (float4), column min/max reduce, normalize from smem, write.
// Single DRAM read + single DRAM write of the tensor.
// ---------------------------------------------------------------------------
__global__ void __launch_bounds__(NT, 2)
cube_norm_kernel(const float* __restrict__ x, float* __restrict__ y) {
    extern __shared__ float sm[];
    float* tile  = sm;                  // TR * DC
    float* pmn   = sm + TR * DC;        // 2 * DC
    float* pmx   = pmn + 2 * DC;        // 2 * DC
    float* s_mid = pmx + 2 * DC;        // DC
    float* s_inv = s_mid + DC;          // DC

    const int g = blockIdx.y;
    if (g >= g_B) return;
    const int c0 = blockIdx.x * DC;
    const int r0 = g_off[g];
    const int nr = g_off[g + 1] - r0;
    if (nr <= 0) return;
    const int tid = threadIdx.x;

    const float* xg = x + (size_t)r0 * D_DIM + c0;
    float*       yg = y + (size_t)r0 * D_DIM + c0;

    const int grp = tid >> 7;       // 0 or 1
    const int col = tid & 127;      // 0..127, active if < DC

    if (nr <= TR) {
        float4* tv = (float4*)tile;
        // ---- load: gmem -> smem, vectorized ----
        if (nr == TR) {
            #pragma unroll
            for (int k = 0; k < (TR * DC4) / NT; k++) {
                int v = tid + k * NT;
                int r = v / DC4;
                int j = v - r * DC4;
                tv[v] = *(const float4*)(xg + (size_t)r * D_DIM + 4 * j);
            }
        } else {
            int nv = nr * DC4;
            for (int v = tid; v < nv; v += NT) {
                int r = v / DC4;
                int j = v - r * DC4;
                tv[v] = *(const float4*)(xg + (size_t)r * D_DIM + 4 * j);
            }
        }
        __syncthreads();

        // ---- column min/max: 2 row-groups of up-to-128 rows each ----
        if (col < DC) {
            float mn =  3.402823466e38f;
            float mx = -3.402823466e38f;
            for (int r = grp; r < nr; r += 2) {
                float v = tile[r * DC + col];
                mn = fminf(mn, v);
                mx = fmaxf(mx, v);
            }
            pmn[grp * DC + col] = mn;
            pmx[grp * DC + col] = mx;
        }
        __syncthreads();
        if (tid < DC) {
            float mn = fminf(pmn[tid], pmn[DC + tid]);
            float mx = fmaxf(pmx[tid], pmx[DC + tid]);
            float m  = (mx + mn) * 0.5f;
            float l  = (mx - mn) * 0.5f;
            l = fmaxf(l, EPSV);
            s_mid[tid] = m;
            s_inv[tid] = 1.0f / l;
        }
        __syncthreads();

        // ---- normalize from smem, write gmem ----
        const float4* mid4 = (const float4*)s_mid;
        const float4* inv4 = (const float4*)s_inv;
        if (nr == TR) {
            #pragma unroll
            for (int k = 0; k < (TR * DC4) / NT; k++) {
                int v = tid + k * NT;
                int r = v / DC4;
                int j = v - r * DC4;
                float4 a = tv[v];
                float4 m = mid4[j];
                float4 iv = inv4[j];
                float4 o;
                o.x = (a.x - m.x) * iv.x;
                o.y = (a.y - m.y) * iv.y;
                o.z = (a.z - m.z) * iv.z;
                o.w = (a.w - m.w) * iv.w;
                *(float4*)(yg + (size_t)r * D_DIM + 4 * j) = o;
            }
        } else {
            int nv = nr * DC4;
            for (int v = tid; v < nv; v += NT) {
                int r = v / DC4;
                int j = v - r * DC4;
                float4 a = tv[v];
                float4 m = mid4[j];
                float4 iv = inv4[j];
                float4 o;
                o.x = (a.x - m.x) * iv.x;
                o.y = (a.y - m.y) * iv.y;
                o.z = (a.z - m.z) * iv.z;
                o.w = (a.w - m.w) * iv.w;
                *(float4*)(yg + (size_t)r * D_DIM + 4 * j) = o;
            }
        }
    } else {
        // ---- fallback for graphs larger than TR rows (not hit by dataset):
        // two direct gmem sweeps.
        if (col < DC) {
            float mn =  3.402823466e38f;
            float mx = -3.402823466e38f;
            for (int r = grp; r < nr; r += 2) {
                float v = xg[(size_t)r * D_DIM + col];
                mn = fminf(mn, v);
                mx = fmaxf(mx, v);
            }
            pmn[grp * DC + col] = mn;
            pmx[grp * DC + col] = mx;
        }
        __syncthreads();
        if (tid < DC) {
            float mn = fminf(pmn[tid], pmn[DC + tid]);
            float mx = fmaxf(pmx[tid], pmx[DC + tid]);
            float m  = (mx + mn) * 0.5f;
            float l  = (mx - mn) * 0.5f;
            l = fmaxf(l, EPSV);
            s_mid[tid] = m;
            s_inv[tid] = 1.0f / l;
        }
        __syncthreads();
        const float4* mid4 = (const float4*)s_mid;
        const float4* inv4 = (const float4*)s_inv;
        long long nv = (long long)nr * DC4;
        for (long long v = tid; v < nv; v += NT) {
            int r = (int)(v / DC4);
            int j = (int)(v - (long long)r * DC4);
            float4 a = *(const float4*)(xg + (size_t)r * D_DIM + 4 * j);
            float4 m = mid4[j];
            float4 iv = inv4[j];
            float4 o;
            o.x = (a.x - m.x) * iv.x;
            o.y = (a.y - m.y) * iv.y;
            o.z = (a.z - m.z) * iv.z;
            o.w = (a.w - m.w) * iv.w;
            *(float4*)(yg + (size_t)r * D_DIM + 4 * j) = o;
        }
    }
}

// ---------------------------------------------------------------------------
extern "C" void kernel_launch(void* const* d_in, const int* in_sizes, int n_in,
                              void* d_out, int out_size) {
    const float* x  = (const float*)d_in[0];
    const int*   bl = (const int*)d_in[1];
    float*       y  = (float*)d_out;

    const int nb   = in_sizes[1];
    const int ntot = in_sizes[0] / D_DIM;

    const int smem = (TR * DC + 6 * DC) * (int)sizeof(float); // 104,800 B
    cudaFuncSetAttribute(cube_norm_kernel,
                         cudaFuncAttributeMaxDynamicSharedMemorySize, smem);

    offsets_kernel<<<1, 1024>>>(bl, nb, ntot);

    int gy = nb < MAXB ? nb : MAXB;
    if (gy < 1) gy = 1;
    dim3 grid(NCHUNK, gy);
    cube_norm_kernel<<<grid, NT, smem>>>(x, y);
}

// round 2
// speedup vs baseline: 1.2505x; 1.2505x over previous
#include <cuda_runtime.h>

// Problem constants (shapes fixed by dataset; code stays correct for any
// batch_list via the offsets kernel + fallback path).
#define D_DIM   300          // embedding dim
#define DC      60           // columns per chunk (multiple of 4, divides 300)
#define DC4     (DC / 4)     // 15 float4 per row-chunk
#define NCHUNK  (D_DIM / DC) // 5
#define TR      256          // row tile (== nodes per graph in this dataset)
#define NT      512          // threads per CTA
#define NGRP    (NT / 64)    // 8 row-groups in the reduce phase
#define MAXB    8192
#define EPSV    1e-12f

// Scratch (no cudaMalloc allowed): per-graph row offsets + actual graph count.
__device__ int g_off[MAXB + 1];
__device__ int g_B;

// ---------------------------------------------------------------------------
// Offsets kernel: detects int32 vs int64 batch_list layout. Fast path: if all
// counts are equal (dataset case), writes offsets arithmetically with no scan.
// Fallback: block-wide inclusive scan.
// ---------------------------------------------------------------------------
__global__ void offsets_kernel(const int* __restrict__ p32, int nb, int ntot) {
    __shared__ int sh[1024];
    __shared__ int s_stride, s_carry, s_uni, s_val;
    const int tid = threadIdx.x;

    if (tid == 0) {
        int stride = 1;
        if (nb > 1) {
            int v0 = p32[0], v1 = p32[1];
            if (v1 == 0 && v0 != 0) stride = 2;   // int64 little-endian
        }
        s_stride = stride;
        s_carry = 0;
        s_uni = 1;
        s_val = p32[0];
        g_off[0] = 0;
    }
    __syncthreads();

    const int st = s_stride;
    int B = nb;
    if (B > MAXB) B = MAXB;
    const int B1 = (st == 2) ? (B >> 1) : B;
    const int v0 = s_val;

    // ---- uniformity check over [0, B1) ----
    int uni = 1;
    for (int i = tid; i < B1; i += 1024)
        if (p32[(size_t)i * st] != v0) uni = 0;
    if (!uni) atomicAnd(&s_uni, 0);
    __syncthreads();

    if (s_uni && (long long)B1 * v0 == ntot) {
        // Fast path: equal-sized graphs.
        for (int i = tid; i < B1; i += 1024)
            g_off[i + 1] = (i + 1) * v0;
        if (tid == 0) g_B = B1;
        return;
    }

    // ---- general path: inclusive scan ----
    for (int base = 0; base < B1; base += 1024) {
        int i = base + tid;
        int v = (i < B1) ? p32[(size_t)i * st] : 0;
        sh[tid] = v;
        __syncthreads();
        #pragma unroll
        for (int o = 1; o < 1024; o <<= 1) {
            int t = (tid >= o) ? sh[tid - o] : 0;
            __syncthreads();
            sh[tid] += t;
            __syncthreads();
        }
        if (i < B1) g_off[i + 1] = s_carry + sh[tid];
        __syncthreads();
        if (tid == 0) s_carry += sh[1023];
        __syncthreads();
    }

    int Bfinal = B1;
    if (st == 2 && B1 > 0 && g_off[B1] != ntot && B > B1) {
        for (int base = B1; base < B; base += 1024) {
            int i = base + tid;
            int v = (i < B) ? p32[(size_t)i * st] : 0;
            sh[tid] = v;
            __syncthreads();
            #pragma unroll
            for (int o = 1; o < 1024; o <<= 1) {
                int t = (tid >= o) ? sh[tid - o] : 0;
                __syncthreads();
                sh[tid] += t;
                __syncthreads();
            }
            if (i < B) g_off[i + 1] = s_carry + sh[tid];
            __syncthreads();
            if (tid == 0) s_carry += sh[1023];
            __syncthreads();
        }
        Bfinal = B;
    }
    if (tid == 0) g_B = Bfinal;
}

// ---------------------------------------------------------------------------
// Main kernel: one CTA per (graph, 60-column chunk). 3 CTAs/SM (61.4KB tile),
// 512 threads: load tile -> smem (streaming float4), column min/max over 8
// row-groups, normalize from smem, streaming write. Single DRAM read + write.
// ---------------------------------------------------------------------------
__global__ void __launch_bounds__(NT, 3)
cube_norm_kernel(const float* __restrict__ x, float* __restrict__ y) {
    extern __shared__ float sm[];
    float* tile  = sm;                   // TR * DC          (15360)
    float* pmn   = sm + TR * DC;         // NGRP * DC        (480)
    float* pmx   = pmn + NGRP * DC;      // NGRP * DC        (480)
    float* s_mid = pmx + NGRP * DC;      // DC               (60)
    float* s_inv = s_mid + DC;           // DC               (60)

    const int g = blockIdx.y;
    if (g >= g_B) return;
    const int c0 = blockIdx.x * DC;
    const int r0 = g_off[g];
    const int nr = g_off[g + 1] - r0;
    if (nr <= 0) return;
    const int tid = threadIdx.x;

    const float* xg = x + (size_t)r0 * D_DIM + c0;
    float*       yg = y + (size_t)r0 * D_DIM + c0;

    const int col = tid & 63;       // 0..63, active if < DC
    const int grp = tid >> 6;       // 0..7

    if (nr <= TR) {
        float4* tv = (float4*)tile;
        // ---- load: gmem -> smem, streaming float4 ----
        if (nr == TR) {
            #pragma unroll
            for (int k = 0; k < 7; k++) {               // 7*512 = 3584
                int v = tid + k * NT;
                int r = v / DC4;
                int j = v - r * DC4;
                tv[v] = __ldcs((const float4*)(xg + (size_t)r * D_DIM + 4 * j));
            }
            {                                            // tail: 3840-3584=256
                int v = tid + 7 * NT;
                if (tid < TR * DC4 - 7 * NT) {
                    int r = v / DC4;
                    int j = v - r * DC4;
                    tv[v] = __ldcs((const float4*)(xg + (size_t)r * D_DIM + 4 * j));
                }
            }
        } else {
            int nv = nr * DC4;
            for (int v = tid; v < nv; v += NT) {
                int r = v / DC4;
                int j = v - r * DC4;
                tv[v] = __ldcs((const float4*)(xg + (size_t)r * D_DIM + 4 * j));
            }
        }
        __syncthreads();

        // ---- column min/max: 8 row-groups ----
        if (col < DC) {
            float mn =  3.402823466e38f;
            float mx = -3.402823466e38f;
            for (int r = grp; r < nr; r += NGRP) {
                float v = tile[r * DC + col];
                mn = fminf(mn, v);
                mx = fmaxf(mx, v);
            }
            pmn[grp * DC + col] = mn;
            pmx[grp * DC + col] = mx;
        }
        __syncthreads();
        if (tid < DC) {
            float mn = pmn[tid], mx = pmx[tid];
            #pragma unroll
            for (int gq = 1; gq < NGRP; gq++) {
                mn = fminf(mn, pmn[gq * DC + tid]);
                mx = fmaxf(mx, pmx[gq * DC + tid]);
            }
            float m = (mx + mn) * 0.5f;
            float l = (mx - mn) * 0.5f;
            l = fmaxf(l, EPSV);
            s_mid[tid] = m;
            s_inv[tid] = 1.0f / l;
        }
        __syncthreads();

        // ---- normalize from smem, streaming write ----
        const float4* mid4 = (const float4*)s_mid;
        const float4* inv4 = (const float4*)s_inv;
        if (nr == TR) {
            #pragma unroll
            for (int k = 0; k < 7; k++) {
                int v = tid + k * NT;
                int r = v / DC4;
                int j = v - r * DC4;
                float4 a = tv[v];
                float4 m = mid4[j];
                float4 iv = inv4[j];
                float4 o;
                o.x = (a.x - m.x) * iv.x;
                o.y = (a.y - m.y) * iv.y;
                o.z = (a.z - m.z) * iv.z;
                o.w = (a.w - m.w) * iv.w;
                __stcs((float4*)(yg + (size_t)r * D_DIM + 4 * j), o);
            }
            {
                int v = tid + 7 * NT;
                if (tid < TR * DC4 - 7 * NT) {
                    int r = v / DC4;
                    int j = v - r * DC4;
                    float4 a = tv[v];
                    float4 m = mid4[j];
                    float4 iv = inv4[j];
                    float4 o;
                    o.x = (a.x - m.x) * iv.x;
                    o.y = (a.y - m.y) * iv.y;
                    o.z = (a.z - m.z) * iv.z;
                    o.w = (a.w - m.w) * iv.w;
                    __stcs((float4*)(yg + (size_t)r * D_DIM + 4 * j), o);
                }
            }
        } else {
            int nv = nr * DC4;
            for (int v = tid; v < nv; v += NT) {
                int r = v / DC4;
                int j = v - r * DC4;
                float4 a = tv[v];
                float4 m = mid4[j];
                float4 iv = inv4[j];
                float4 o;
                o.x = (a.x - m.x) * iv.x;
                o.y = (a.y - m.y) * iv.y;
                o.z = (a.z - m.z) * iv.z;
                o.w = (a.w - m.w) * iv.w;
                __stcs((float4*)(yg + (size_t)r * D_DIM + 4 * j), o);
            }
        }
    } else {
        // ---- fallback for graphs larger than TR rows (not hit by dataset):
        // two direct gmem sweeps.
        if (col < DC) {
            float mn =  3.402823466e38f;
            float mx = -3.402823466e38f;
            for (int r = grp; r < nr; r += NGRP) {
                float v = xg[(size_t)r * D_DIM + col];
                mn = fminf(mn, v);
                mx = fmaxf(mx, v);
            }
            pmn[grp * DC + col] = mn;
            pmx[grp * DC + col] = mx;
        }
        __syncthreads();
        if (tid < DC) {
            float mn = pmn[tid], mx = pmx[tid];
            #pragma unroll
            for (int gq = 1; gq < NGRP; gq++) {
                mn = fminf(mn, pmn[gq * DC + tid]);
                mx = fmaxf(mx, pmx[gq * DC + tid]);
            }
            float m = (mx + mn) * 0.5f;
            float l = (mx - mn) * 0.5f;
            l = fmaxf(l, EPSV);
            s_mid[tid] = m;
            s_inv[tid] = 1.0f / l;
        }
        __syncthreads();
        const float4* mid4 = (const float4*)s_mid;
        const float4* inv4 = (const float4*)s_inv;
        long long nv = (long long)nr * DC4;
        for (long long v = tid; v < nv; v += NT) {
            int r = (int)(v / DC4);
            int j = (int)(v - (long long)r * DC4);
            float4 a = *(const float4*)(xg + (size_t)r * D_DIM + 4 * j);
            float4 m = mid4[j];
            float4 iv = inv4[j];
            float4 o;
            o.x = (a.x - m.x) * iv.x;
            o.y = (a.y - m.y) * iv.y;
            o.z = (a.z - m.z) * iv.z;
            o.w = (a.w - m.w) * iv.w;
            *(float4*)(yg + (size_t)r * D_DIM + 4 * j) = o;
        }
    }
}

// ---------------------------------------------------------------------------
extern "C" void kernel_launch(void* const* d_in, const int* in_sizes, int n_in,
                              void* d_out, int out_size) {
    const float* x  = (const float*)d_in[0];
    const int*   bl = (const int*)d_in[1];
    float*       y  = (float*)d_out;

    const int nb   = in_sizes[1];
    const int ntot = in_sizes[0] / D_DIM;

    const int smem = (TR * DC + 2 * NGRP * DC + 2 * DC) * (int)sizeof(float); // 65,760 B
    cudaFuncSetAttribute(cube_norm_kernel,
                         cudaFuncAttributeMaxDynamicSharedMemorySize, smem);

    offsets_kernel<<<1, 1024>>>(bl, nb, ntot);

    int gy = nb < MAXB ? nb : MAXB;
    if (gy < 1) gy = 1;
    dim3 grid(NCHUNK, gy);
    cube_norm_kernel<<<grid, NT, smem>>>(x, y);
}

// round 3
// speedup vs baseline: 1.5347x; 1.2272x over previous
#include <cuda_runtime.h>

// Problem constants (shapes fixed by dataset; code stays correct for any
// batch_list via the offsets kernel + generic path).
#define D_DIM   300          // embedding dim
#define DC      60           // columns per chunk (multiple of 4, divides 300)
#define DC4     (DC / 4)     // 15 float4 per row-chunk
#define NCHUNK  (D_DIM / DC) // 5
#define TR      256          // row tile (== nodes per graph in this dataset)
#define NT      480          // threads per CTA = 32 row-blocks * 15 col-quads
#define RB      32           // row-blocks
#define KIT     (TR / RB)    // 8 rows per thread in fast path
#define MAXB    8192
#define EPSV    1e-12f

// Scratch (no cudaMalloc allowed): per-graph row offsets + actual graph count.
__device__ int g_off[MAXB + 1];
__device__ int g_B;

// ---------------------------------------------------------------------------
// Offsets kernel: detects int32 vs int64 batch_list layout. Fast path: if all
// counts are equal (dataset case), writes offsets arithmetically with no scan.
// Fallback: block-wide inclusive scan.
// ---------------------------------------------------------------------------
__global__ void offsets_kernel(const int* __restrict__ p32, int nb, int ntot) {
    __shared__ int sh[1024];
    __shared__ int s_stride, s_carry, s_uni, s_val;
    const int tid = threadIdx.x;

    if (tid == 0) {
        int stride = 1;
        if (nb > 1) {
            int v0 = p32[0], v1 = p32[1];
            if (v1 == 0 && v0 != 0) stride = 2;   // int64 little-endian
        }
        s_stride = stride;
        s_carry = 0;
        s_uni = 1;
        s_val = p32[0];
        g_off[0] = 0;
    }
    __syncthreads();

    const int st = s_stride;
    int B = nb;
    if (B > MAXB) B = MAXB;
    const int B1 = (st == 2) ? (B >> 1) : B;
    const int v0 = s_val;

    int uni = 1;
    for (int i = tid; i < B1; i += 1024)
        if (p32[(size_t)i * st] != v0) uni = 0;
    if (!uni) atomicAnd(&s_uni, 0);
    __syncthreads();

    if (s_uni && (long long)B1 * v0 == ntot) {
        for (int i = tid; i < B1; i += 1024)
            g_off[i + 1] = (i + 1) * v0;
        if (tid == 0) g_B = B1;
        return;
    }

    for (int base = 0; base < B1; base += 1024) {
        int i = base + tid;
        int v = (i < B1) ? p32[(size_t)i * st] : 0;
        sh[tid] = v;
        __syncthreads();
        #pragma unroll
        for (int o = 1; o < 1024; o <<= 1) {
            int t = (tid >= o) ? sh[tid - o] : 0;
            __syncthreads();
            sh[tid] += t;
            __syncthreads();
        }
        if (i < B1) g_off[i + 1] = s_carry + sh[tid];
        __syncthreads();
        if (tid == 0) s_carry += sh[1023];
        __syncthreads();
    }

    int Bfinal = B1;
    if (st == 2 && B1 > 0 && g_off[B1] != ntot && B > B1) {
        for (int base = B1; base < B; base += 1024) {
            int i = base + tid;
            int v = (i < B) ? p32[(size_t)i * st] : 0;
            sh[tid] = v;
            __syncthreads();
            #pragma unroll
            for (int o = 1; o < 1024; o <<= 1) {
                int t = (tid >= o) ? sh[tid - o] : 0;
                __syncthreads();
                sh[tid] += t;
                __syncthreads();
            }
            if (i < B) g_off[i + 1] = s_carry + sh[tid];
            __syncthreads();
            if (tid == 0) s_carry += sh[1023];
            __syncthreads();
        }
        Bfinal = B;
    }
    if (tid == 0) g_B = Bfinal;
}

// ---------------------------------------------------------------------------
// Helpers
// ---------------------------------------------------------------------------
__device__ __forceinline__ float4 min4(float4 a, float4 b) {
    return make_float4(fminf(a.x, b.x), fminf(a.y, b.y),
                       fminf(a.z, b.z), fminf(a.w, b.w));
}
__device__ __forceinline__ float4 max4(float4 a, float4 b) {
    return make_float4(fmaxf(a.x, b.x), fmaxf(a.y, b.y),
                       fmaxf(a.z, b.z), fmaxf(a.w, b.w));
}

// ---------------------------------------------------------------------------
// Main kernel: one CTA per (graph, 60-column chunk). Register-resident:
// thread (rb = tid/15, j = tid%15) loads rows rb+32k of column-quad j into
// registers, reducing min/max in-flight. Only 15KB of partials touch smem.
// Normalize happens from registers; single DRAM read + single DRAM write.
// ---------------------------------------------------------------------------
__global__ void __launch_bounds__(NT, 2)
cube_norm_kernel(const float* __restrict__ x, float* __restrict__ y) {
    __shared__ float4 s_mn[RB][DC4];   // 15360 B total for both
    __shared__ float4 s_mx[RB][DC4];

    const int g = blockIdx.y;
    if (g >= g_B) return;
    const int c0 = blockIdx.x * DC;
    const int r0 = g_off[g];
    const int nr = g_off[g + 1] - r0;
    if (nr <= 0) return;

    const int tid = threadIdx.x;
    const int j   = tid % DC4;         // column quad 0..14
    const int rb  = tid / DC4;         // row block 0..31

    const float* xg = x + (size_t)r0 * D_DIM + c0 + 4 * j;
    float*       yg = y + (size_t)r0 * D_DIM + c0 + 4 * j;

    if (nr == TR) {
        // ---------------- fast register-resident path ----------------
        float4 v[KIT];
        const float* p = xg + (size_t)rb * D_DIM;
        #pragma unroll
        for (int k = 0; k < KIT; k++)
            v[k] = __ldcs((const float4*)(p + (size_t)k * RB * D_DIM));

        float4 mn = v[0], mx = v[0];
        #pragma unroll
        for (int k = 1; k < KIT; k++) {
            mn = min4(mn, v[k]);
            mx = max4(mx, v[k]);
        }
        s_mn[rb][j] = mn;
        s_mx[rb][j] = mx;
        __syncthreads();

        // tree reduce over row blocks
        #pragma unroll
        for (int s = RB / 2; s >= 1; s >>= 1) {
            if (rb < s) {
                s_mn[rb][j] = min4(s_mn[rb][j], s_mn[rb + s][j]);
                s_mx[rb][j] = max4(s_mx[rb][j], s_mx[rb + s][j]);
            }
            __syncthreads();
        }

        float4 fmn = s_mn[0][j];
        float4 fmx = s_mx[0][j];
        float4 mid = make_float4((fmx.x + fmn.x) * 0.5f, (fmx.y + fmn.y) * 0.5f,
                                 (fmx.z + fmn.z) * 0.5f, (fmx.w + fmn.w) * 0.5f);
        float4 inv = make_float4(
            1.0f / fmaxf((fmx.x - fmn.x) * 0.5f, EPSV),
            1.0f / fmaxf((fmx.y - fmn.y) * 0.5f, EPSV),
            1.0f / fmaxf((fmx.z - fmn.z) * 0.5f, EPSV),
            1.0f / fmaxf((fmx.w - fmn.w) * 0.5f, EPSV));

        float* q = yg + (size_t)rb * D_DIM;
        #pragma unroll
        for (int k = 0; k < KIT; k++) {
            float4 o;
            o.x = (v[k].x - mid.x) * inv.x;
            o.y = (v[k].y - mid.y) * inv.y;
            o.z = (v[k].z - mid.z) * inv.z;
            o.w = (v[k].w - mid.w) * inv.w;
            __stcs((float4*)(q + (size_t)k * RB * D_DIM), o);
        }
    } else {
        // ---------------- generic two-sweep path (not hit by dataset) ------
        float4 mn = make_float4( 3.402823466e38f,  3.402823466e38f,
                                 3.402823466e38f,  3.402823466e38f);
        float4 mx = make_float4(-3.402823466e38f, -3.402823466e38f,
                                -3.402823466e38f, -3.402823466e38f);
        for (int r = rb; r < nr; r += RB) {
            float4 a = *(const float4*)(xg + (size_t)r * D_DIM);
            mn = min4(mn, a);
            mx = max4(mx, a);
        }
        s_mn[rb][j] = mn;
        s_mx[rb][j] = mx;
        __syncthreads();
        #pragma unroll
        for (int s = RB / 2; s >= 1; s >>= 1) {
            if (rb < s) {
                s_mn[rb][j] = min4(s_mn[rb][j], s_mn[rb + s][j]);
                s_mx[rb][j] = max4(s_mx[rb][j], s_mx[rb + s][j]);
            }
            __syncthreads();
        }
        float4 fmn = s_mn[0][j];
        float4 fmx = s_mx[0][j];
        float4 mid = make_float4((fmx.x + fmn.x) * 0.5f, (fmx.y + fmn.y) * 0.5f,
                                 (fmx.z + fmn.z) * 0.5f, (fmx.w + fmn.w) * 0.5f);
        float4 inv = make_float4(
            1.0f / fmaxf((fmx.x - fmn.x) * 0.5f, EPSV),
            1.0f / fmaxf((fmx.y - fmn.y) * 0.5f, EPSV),
            1.0f / fmaxf((fmx.z - fmn.z) * 0.5f, EPSV),
            1.0f / fmaxf((fmx.w - fmn.w) * 0.5f, EPSV));
        for (int r = rb; r < nr; r += RB) {
            float4 a = *(const float4*)(xg + (size_t)r * D_DIM);
            float4 o;
            o.x = (a.x - mid.x) * inv.x;
            o.y = (a.y - mid.y) * inv.y;
            o.z = (a.z - mid.z) * inv.z;
            o.w = (a.w - mid.w) * inv.w;
            *(float4*)(yg + (size_t)r * D_DIM) = o;
        }
    }
}

// ---------------------------------------------------------------------------
extern "C" void kernel_launch(void* const* d_in, const int* in_sizes, int n_in,
                              void* d_out, int out_size) {
    const float* x  = (const float*)d_in[0];
    const int*   bl = (const int*)d_in[1];
    float*       y  = (float*)d_out;

    const int nb   = in_sizes[1];
    const int ntot = in_sizes[0] / D_DIM;

    offsets_kernel<<<1, 1024>>>(bl, nb, ntot);

    int gy = nb < MAXB ? nb : MAXB;
    if (gy < 1) gy = 1;
    dim3 grid(NCHUNK, gy);
    cube_norm_kernel<<<grid, NT>>>(x, y);
}